// round 6
// baseline (speedup 1.0000x reference)
#include <cuda_runtime.h>
#include <cstdint>

// RadarSparseProcessor: out[v,o] = (sum_p sum_c x[v,p,c] * W[o,c]) / max(n_v, 1)
// V = 1048576, P = 4, C_IN = 4, C_OUT = 32. vnp is int32.
//
// R6: bulk-async tiling. Persistent blocks (2/SM), double-buffered
// cp.async.bulk loads (16KB+1KB per tile) and bulk_group stores (32KB per
// tile). SM side = R5's conflict-free LDS/shfl/STS pipeline. Goal: large
// contiguous DRAM bursts per stream to break the ~52% mixed-r/w cap.

#define THREADS 256
#define VPT 256                      // voxels per tile
#define IN_BYTES  (VPT * 16 * 4)     // 16384
#define NP_BYTES  (VPT * 4)          // 1024
#define OUT_BYTES (VPT * 32 * 4)     // 32768

struct __align__(128) Smem {
    float4   inA[2][VPT * 4];        // 2 x 16 KB
    float4   outB[2][VPT * 8];       // 2 x 32 KB
    int      np[2][VPT];             // 2 x 1 KB
    uint64_t mbar[2];
};

__device__ __forceinline__ uint32_t smem_u32(const void* p) {
    return (uint32_t)__cvta_generic_to_shared(p);
}

__device__ __forceinline__ void mbar_init(uint32_t mbar, uint32_t count) {
    asm volatile("mbarrier.init.shared.b64 [%0], %1;" :: "r"(mbar), "r"(count) : "memory");
}
__device__ __forceinline__ void mbar_expect_tx(uint32_t mbar, uint32_t bytes) {
    asm volatile("mbarrier.arrive.expect_tx.shared.b64 _, [%0], %1;"
                 :: "r"(mbar), "r"(bytes) : "memory");
}
__device__ __forceinline__ void mbar_wait(uint32_t mbar, uint32_t parity) {
    asm volatile(
        "{\n\t.reg .pred P;\n"
        "W%=:\n\tmbarrier.try_wait.parity.acquire.cta.shared::cta.b64 P, [%0], %1, 0x989680;\n"
        "\t@P bra D%=;\n\tbra W%=;\nD%=:\n\t}"
        :: "r"(mbar), "r"(parity) : "memory");
}
__device__ __forceinline__ void bulk_load(uint32_t dst_smem, const void* src, uint32_t bytes,
                                          uint32_t mbar) {
    asm volatile(
        "cp.async.bulk.shared::cta.global.mbarrier::complete_tx::bytes [%0], [%1], %2, [%3];"
        :: "r"(dst_smem), "l"(src), "r"(bytes), "r"(mbar) : "memory");
}
__device__ __forceinline__ void bulk_store(void* dst, uint32_t src_smem, uint32_t bytes) {
    asm volatile("cp.async.bulk.global.shared::cta.bulk_group [%0], [%1], %2;"
                 :: "l"(dst), "r"(src_smem), "r"(bytes) : "memory");
}
__device__ __forceinline__ void bulk_commit() {
    asm volatile("cp.async.bulk.commit_group;" ::: "memory");
}
template <int N>
__device__ __forceinline__ void bulk_wait_read() {
    asm volatile("cp.async.bulk.wait_group.read %0;" :: "n"(N) : "memory");
}
template <int N>
__device__ __forceinline__ void bulk_wait() {
    asm volatile("cp.async.bulk.wait_group %0;" :: "n"(N) : "memory");
}

__global__ __launch_bounds__(THREADS)
void radar_sparse_kernel(const float4* __restrict__ in4,  // [V*4] float4
                         const float4* __restrict__ W4,   // [32] float4
                         const int*    __restrict__ vnp,  // [V] int32
                         float4* __restrict__ out4,       // [V*8] float4
                         int V, int ntiles)
{
    extern __shared__ char smem_raw[];
    Smem* sm = reinterpret_cast<Smem*>(smem_raw);

    const unsigned FULL = 0xFFFFFFFFu;
    const int tid  = threadIdx.x;
    const int lane = tid & 31;
    const int w    = tid >> 5;

    // Per-lane weight rows for channel quad q (channels 4q..4q+3)
    const int q = lane & 7;
    const float4 w0 = W4[q * 4 + 0];
    const float4 w1 = W4[q * 4 + 1];
    const float4 w2 = W4[q * 4 + 2];
    const float4 w3 = W4[q * 4 + 3];

    const uint32_t mb0 = smem_u32(&sm->mbar[0]);
    const uint32_t mb1 = smem_u32(&sm->mbar[1]);

    if (tid == 0) { mbar_init(mb0, 1); mbar_init(mb1, 1); }
    __syncthreads();

    // Prefetch first tile into buf 0
    const int tile0 = blockIdx.x;
    if (tid == 0 && tile0 < ntiles) {
        mbar_expect_tx(mb0, IN_BYTES + NP_BYTES);
        bulk_load(smem_u32(sm->inA[0]), in4 + (size_t)tile0 * (VPT * 4), IN_BYTES, mb0);
        bulk_load(smem_u32(sm->np[0]),  vnp + (size_t)tile0 * VPT,        NP_BYTES, mb0);
    }

    int it = 0;
    for (int tile = blockIdx.x; tile < ntiles; tile += gridDim.x, it++) {
        const int buf    = it & 1;
        const int parity = (it >> 1) & 1;
        const uint32_t mb = buf ? mb1 : mb0;

        // Prefetch tile it+1 into the other buffer (its previous compute is done)
        const int ntile = tile + gridDim.x;
        if (tid == 0 && ntile < ntiles) {
            const int nbuf = buf ^ 1;
            const uint32_t nmb = nbuf ? mb1 : mb0;
            mbar_expect_tx(nmb, IN_BYTES + NP_BYTES);
            bulk_load(smem_u32(sm->inA[nbuf]), in4 + (size_t)ntile * (VPT * 4), IN_BYTES, nmb);
            bulk_load(smem_u32(sm->np[nbuf]),  vnp + (size_t)ntile * VPT,        NP_BYTES, nmb);
        }

        // Wait for this tile's data; ensure outB[buf] has been fully read by
        // the TMA store of tile it-2 (<=1 outstanding unread store group).
        mbar_wait(mb, parity);
        if (tid == 0) bulk_wait_read<1>();
        __syncthreads();

        // ---- Compute (R5 lane mapping, all smem conflict-free) ----
        const float4* inT = sm->inA[buf] + w * 128;
        int n = sm->np[buf][w * 32 + lane];
        float invl = 1.0f / (float)(n > 1 ? n : 1);

        float4 s[4];
        #pragma unroll
        for (int k = 0; k < 4; k++) {
            float4 d = inT[k * 32 + lane];
            d.x += __shfl_xor_sync(FULL, d.x, 1);
            d.y += __shfl_xor_sync(FULL, d.y, 1);
            d.z += __shfl_xor_sync(FULL, d.z, 1);
            d.w += __shfl_xor_sync(FULL, d.w, 1);
            d.x += __shfl_xor_sync(FULL, d.x, 2);
            d.y += __shfl_xor_sync(FULL, d.y, 2);
            d.z += __shfl_xor_sync(FULL, d.z, 2);
            d.w += __shfl_xor_sync(FULL, d.w, 2);
            float ik = __shfl_sync(FULL, invl, 8 * k + (lane >> 2));
            d.x *= ik; d.y *= ik; d.z *= ik; d.w *= ik;
            s[k] = d;
        }

        float4* outT = sm->outB[buf] + w * 256;
        #pragma unroll
        for (int i2 = 0; i2 < 8; i2++) {
            const int k   = i2 >> 1;
            const int src = 16 * (i2 & 1) + 4 * (lane >> 3);
            float4 sv;
            sv.x = __shfl_sync(FULL, s[k].x, src);
            sv.y = __shfl_sync(FULL, s[k].y, src);
            sv.z = __shfl_sync(FULL, s[k].z, src);
            sv.w = __shfl_sync(FULL, s[k].w, src);
            float4 o;
            o.x = fmaf(w0.x, sv.x, fmaf(w0.y, sv.y, fmaf(w0.z, sv.z, w0.w * sv.w)));
            o.y = fmaf(w1.x, sv.x, fmaf(w1.y, sv.y, fmaf(w1.z, sv.z, w1.w * sv.w)));
            o.z = fmaf(w2.x, sv.x, fmaf(w2.y, sv.y, fmaf(w2.z, sv.z, w2.w * sv.w)));
            o.w = fmaf(w3.x, sv.x, fmaf(w3.y, sv.y, fmaf(w3.z, sv.z, w3.w * sv.w)));
            outT[i2 * 32 + lane] = o;                 // STS.128, conflict-free
        }
        __syncthreads();                              // all STS visible

        if (tid == 0) {
            asm volatile("fence.proxy.async.shared::cta;" ::: "memory");
            bulk_store(out4 + (size_t)tile * (VPT * 8), smem_u32(sm->outB[buf]), OUT_BYTES);
            bulk_commit();
        }
    }

    // Drain all stores before smem is torn down / kernel ends.
    if (tid == 0) bulk_wait<0>();
    __syncthreads();

    // ---- Tail: voxels not covered by full tiles (none for V = 1M) ----
    const int rem0 = ntiles * VPT;
    for (int v = rem0 + blockIdx.x * blockDim.x + tid; v < V;
         v += gridDim.x * blockDim.x) {
        const float4* vrow = in4 + (size_t)v * 4;
        float4 p0 = vrow[0], p1 = vrow[1], p2 = vrow[2], p3 = vrow[3];
        int n = vnp[v];
        float inv = 1.0f / (float)(n > 1 ? n : 1);
        float sx = ((p0.x + p1.x) + (p2.x + p3.x)) * inv;
        float sy = ((p0.y + p1.y) + (p2.y + p3.y)) * inv;
        float sz = ((p0.z + p1.z) + (p2.z + p3.z)) * inv;
        float sw = ((p0.w + p1.w) + (p2.w + p3.w)) * inv;
        float4* orow = out4 + (size_t)v * 8;
        #pragma unroll
        for (int kk = 0; kk < 8; kk++) {
            float4 a = W4[kk * 4 + 0], b = W4[kk * 4 + 1];
            float4 c = W4[kk * 4 + 2], d = W4[kk * 4 + 3];
            float4 o;
            o.x = fmaf(a.x, sx, fmaf(a.y, sy, fmaf(a.z, sz, a.w * sw)));
            o.y = fmaf(b.x, sx, fmaf(b.y, sy, fmaf(b.z, sz, b.w * sw)));
            o.z = fmaf(c.x, sx, fmaf(c.y, sy, fmaf(c.z, sz, c.w * sw)));
            o.w = fmaf(d.x, sx, fmaf(d.y, sy, fmaf(d.z, sz, d.w * sw)));
            orow[kk] = o;
        }
    }
}

extern "C" void kernel_launch(void* const* d_in, const int* in_sizes, int n_in,
                              void* d_out, int out_size)
{
    const float4* in4 = (const float4*)d_in[0];   // voxel_features [V,4,4] f32
    const float4* W4  = (const float4*)d_in[1];   // W [32,4] f32
    const int*    vnp = (const int*)d_in[2];      // voxel_num_points [V] i32
    float4*       out = (float4*)d_out;           // [V,32] f32

    int V = in_sizes[2];
    int ntiles = V / VPT;

    static int smem_set = 0;
    if (!smem_set) {
        cudaFuncSetAttribute(radar_sparse_kernel,
                             cudaFuncAttributeMaxDynamicSharedMemorySize,
                             (int)sizeof(Smem));
        smem_set = 1;
    }

    int blocks = 296;                             // 2 per SM (148 SMs)
    if (ntiles > 0 && ntiles < blocks) blocks = ntiles;
    if (ntiles == 0) blocks = (V + THREADS - 1) / THREADS > 0 ? (V + THREADS - 1) / THREADS : 1;

    radar_sparse_kernel<<<blocks, THREADS, sizeof(Smem)>>>(in4, W4, vnp, out, V, ntiles);
}

// round 8
// speedup vs baseline: 1.2657x; 1.2657x over previous
#include <cuda_runtime.h>

// RadarSparseProcessor: out[v,o] = (sum_p sum_c x[v,p,c] * W[o,c]) / max(n_v, 1)
// V = 1048576, P = 4, C_IN = 4, C_OUT = 32. vnp is int32.
//
// R7b (R7 resubmit after infra failure): R5 warp-autonomous shfl transpose
// + streaming cache hints (__ldcs/__stcs on all single-use streams)
// + interleaved per-k stores to cut register pressure (launch_bounds 256x5).
// Traffic is irreducible (196 MB); this targets the DRAM/L2 scheduling
// margin on the mixed 1:2 read:write stream.

#define THREADS 256

__global__ __launch_bounds__(THREADS, 5)
void radar_sparse_kernel(const float4* __restrict__ in4,  // [V*4] float4 (= [V,4,4])
                         const float4* __restrict__ W4,   // [32] float4 (= [32,4])
                         const int*    __restrict__ vnp,  // [V] int32
                         float4* __restrict__ out4,       // [V*8] float4 (= [V,32])
                         int V)
{
    const unsigned FULL = 0xFFFFFFFFu;
    const int lane  = threadIdx.x & 31;
    const int gwarp = (blockIdx.x * blockDim.x + threadIdx.x) >> 5;
    const int vbase = gwarp * 32;                 // first voxel of this warp
    if (vbase >= V) return;

    // Weight rows for this lane's channel quad q = lane&7 (channels 4q..4q+3).
    const int q = lane & 7;
    const float4 w0 = W4[q * 4 + 0];
    const float4 w1 = W4[q * 4 + 1];
    const float4 w2 = W4[q * 4 + 2];
    const float4 w3 = W4[q * 4 + 3];

    if (vbase + 32 <= V) {
        // ---------- fast path: full warp of 32 voxels ----------
        int n = __ldcs(vnp + vbase + lane);       // coalesced 128 B, streaming
        float invl = 1.0f / (float)(n > 1 ? n : 1);

        // Front-batched streaming loads: 4x LDG.128.CS, contiguous 2048 B/warp.
        // Iter k, lane l holds point (l&3) of voxel 8k + (l>>2).
        const float4* inBase = in4 + (size_t)vbase * 4;
        float4 d[4];
        #pragma unroll
        for (int k = 0; k < 4; k++) d[k] = __ldcs(inBase + k * 32 + lane);

        float4* outBase = out4 + (size_t)vbase * 8;

        #pragma unroll
        for (int k = 0; k < 4; k++) {
            // Butterfly sum over the point dimension (4-lane groups).
            float4 s = d[k];
            s.x += __shfl_xor_sync(FULL, s.x, 1);
            s.y += __shfl_xor_sync(FULL, s.y, 1);
            s.z += __shfl_xor_sync(FULL, s.z, 1);
            s.w += __shfl_xor_sync(FULL, s.w, 1);
            s.x += __shfl_xor_sync(FULL, s.x, 2);
            s.y += __shfl_xor_sync(FULL, s.y, 2);
            s.z += __shfl_xor_sync(FULL, s.z, 2);
            s.w += __shfl_xor_sync(FULL, s.w, 2);
            // Fold in 1/max(n,1) of voxel 8k + (l>>2).
            float ik = __shfl_sync(FULL, invl, 8 * k + (lane >> 2));
            s.x *= ik; s.y *= ik; s.z *= ik; s.w *= ik;
            // All 4 lanes of group j=(l>>2) now hold s of voxel 8k+j.

            // Two store iterations i = 2k, 2k+1; iter i covers voxels 4i..4i+3.
            // Lane l writes voxel 4i+(l>>3), channel quad q; s source lane 16h+4(l>>3).
            #pragma unroll
            for (int h = 0; h < 2; h++) {
                const int i   = 2 * k + h;
                const int src = 16 * h + 4 * (lane >> 3);
                float4 sv;
                sv.x = __shfl_sync(FULL, s.x, src);
                sv.y = __shfl_sync(FULL, s.y, src);
                sv.z = __shfl_sync(FULL, s.z, src);
                sv.w = __shfl_sync(FULL, s.w, src);
                float4 o;
                o.x = fmaf(w0.x, sv.x, fmaf(w0.y, sv.y, fmaf(w0.z, sv.z, w0.w * sv.w)));
                o.y = fmaf(w1.x, sv.x, fmaf(w1.y, sv.y, fmaf(w1.z, sv.z, w1.w * sv.w)));
                o.z = fmaf(w2.x, sv.x, fmaf(w2.y, sv.y, fmaf(w2.z, sv.z, w2.w * sv.w)));
                o.w = fmaf(w3.x, sv.x, fmaf(w3.y, sv.y, fmaf(w3.z, sv.z, w3.w * sv.w)));
                __stcs(outBase + i * 32 + lane, o);   // contiguous 512 B/warp, streaming
            }
        }
    } else {
        // ---------- tail path: per-lane scalar (absent for V = 1M) ----------
        int v = vbase + lane;
        if (v < V) {
            const float4* vrow = in4 + (size_t)v * 4;
            float4 p0 = vrow[0], p1 = vrow[1], p2 = vrow[2], p3 = vrow[3];
            int n = vnp[v];
            float inv = 1.0f / (float)(n > 1 ? n : 1);
            float sx = ((p0.x + p1.x) + (p2.x + p3.x)) * inv;
            float sy = ((p0.y + p1.y) + (p2.y + p3.y)) * inv;
            float sz = ((p0.z + p1.z) + (p2.z + p3.z)) * inv;
            float sw = ((p0.w + p1.w) + (p2.w + p3.w)) * inv;
            float4* orow = out4 + (size_t)v * 8;
            #pragma unroll
            for (int kk = 0; kk < 8; kk++) {
                float4 a = W4[kk * 4 + 0], b = W4[kk * 4 + 1];
                float4 c = W4[kk * 4 + 2], e = W4[kk * 4 + 3];
                float4 o;
                o.x = fmaf(a.x, sx, fmaf(a.y, sy, fmaf(a.z, sz, a.w * sw)));
                o.y = fmaf(b.x, sx, fmaf(b.y, sy, fmaf(b.z, sz, b.w * sw)));
                o.z = fmaf(c.x, sx, fmaf(c.y, sy, fmaf(c.z, sz, c.w * sw)));
                o.w = fmaf(e.x, sx, fmaf(e.y, sy, fmaf(e.z, sz, e.w * sw)));
                orow[kk] = o;
            }
        }
    }
}

extern "C" void kernel_launch(void* const* d_in, const int* in_sizes, int n_in,
                              void* d_out, int out_size)
{
    const float4* in4 = (const float4*)d_in[0];   // voxel_features [V,4,4] f32
    const float4* W4  = (const float4*)d_in[1];   // W [32,4] f32
    const int*    vnp = (const int*)d_in[2];      // voxel_num_points [V] i32
    float4*       out = (float4*)d_out;           // [V,32] f32

    int V = in_sizes[2];
    int warps = (V + 31) / 32;
    int blocks = (warps * 32 + THREADS - 1) / THREADS;
    radar_sparse_kernel<<<blocks, THREADS>>>(in4, W4, vnp, out, V);
}